// round 9
// baseline (speedup 1.0000x reference)
#include <cuda_runtime.h>

#define N_NODES 50000
#define N_EDGES 800000
#define D 64
#define NLAYERS 4
#define NGRAPHS 128
#define PAD 68
#define PADW 68
#define CAP 64   // max in-degree slots; Poisson(16) -> P(deg>=64) ~ 1e-21

// Scratch (all __device__ globals per harness rules)
__device__ float4 g_bufA[N_NODES * (D / 4)];
__device__ float4 g_bufB[N_NODES * (D / 4)];
__device__ int g_counts[2][N_NODES];
__device__ int g_bucket[2][N_NODES * CAP];

// ---------------------------------------------------------------------------
// Packed f32x2 helpers (FFMA2 — only reachable via PTX fma.rn.f32x2)
// ---------------------------------------------------------------------------
typedef unsigned long long u64t;
__device__ __forceinline__ u64t pk2(float lo, float hi) {
    u64t r; asm("mov.b64 %0, {%1, %2};" : "=l"(r) : "f"(lo), "f"(hi)); return r;
}
__device__ __forceinline__ void upk2(float& lo, float& hi, u64t v) {
    asm("mov.b64 {%0, %1}, %2;" : "=f"(lo), "=f"(hi) : "l"(v));
}
__device__ __forceinline__ void fma2(u64t& d, u64t a, u64t b) {
    asm("fma.rn.f32x2 %0, %1, %2, %3;" : "=l"(d) : "l"(a), "l"(b), "l"(d));
}

// ---------------------------------------------------------------------------
// Scan-free adjacency build: fixed-capacity buckets, rebuilt every launch.
// ---------------------------------------------------------------------------
__global__ void zero_counts_kernel(int* c0, int* c1) {
    int i = blockIdx.x * blockDim.x + threadIdx.x;
    if (i < N_NODES) { c0[i] = 0; c1[i] = 0; }
}

__global__ void build_kernel(const int* __restrict__ src0, const int* __restrict__ dst0,
                             const int* __restrict__ src1, const int* __restrict__ dst1,
                             int* c0, int* c1, int* b0, int* b1) {
    int e = blockIdx.x * blockDim.x + threadIdx.x;
    if (e >= N_EDGES) return;
    if (blockIdx.y == 0) {
        int d = dst0[e];
        int slot = atomicAdd(&c0[d], 1);
        if (slot < CAP) b0[d * CAP + slot] = src0[e];
    } else {
        int d = dst1[e];
        int slot = atomicAdd(&c1[d], 1);
        if (slot < CAP) b1[d * CAP + slot] = src1[e];
    }
}

// ---------------------------------------------------------------------------
// GIN aggregate as pure gather: out[n] = x[n] + sum_{e: dst=n} x[src[e]]
// ---------------------------------------------------------------------------
__global__ void gather_kernel(const float4* __restrict__ x,
                              const int* __restrict__ cnt,
                              const int* __restrict__ bucket,
                              float4* __restrict__ out) {
    int lane = threadIdx.x & 15;
    int n = blockIdx.x * 16 + (threadIdx.x >> 4);
    if (n >= N_NODES) return;
    int deg = cnt[n];
    if (deg > CAP) deg = CAP;
    const int* __restrict__ lst = bucket + n * CAP;
    float4 acc = x[n * 16 + lane];
    int j = 0;
    for (; j + 4 <= deg; j += 4) {
        int s0 = lst[j];
        int s1 = lst[j + 1];
        int s2 = lst[j + 2];
        int s3 = lst[j + 3];
        float4 v0 = x[s0 * 16 + lane];
        float4 v1 = x[s1 * 16 + lane];
        float4 v2 = x[s2 * 16 + lane];
        float4 v3 = x[s3 * 16 + lane];
        acc.x += (v0.x + v1.x) + (v2.x + v3.x);
        acc.y += (v0.y + v1.y) + (v2.y + v3.y);
        acc.z += (v0.z + v1.z) + (v2.z + v3.z);
        acc.w += (v0.w + v1.w) + (v2.w + v3.w);
    }
    for (; j < deg; j++) {
        int s = lst[j];
        float4 v = x[s * 16 + lane];
        acc.x += v.x; acc.y += v.y; acc.z += v.z; acc.w += v.w;
    }
    out[n * 16 + lane] = acc;
}

// ---------------------------------------------------------------------------
// out = relu(in @ W^T + b) via packed FFMA2.
// 128-node tile, 256 threads; each thread: 4 nodes x 8 adjacent dims
// (16 f32x2 accumulators). W staged k-major so dim pairs are contiguous.
// In-place safe (tile staged via smem before any store by this block).
// ---------------------------------------------------------------------------
__global__ void __launch_bounds__(256, 3)
gemm_relu_kernel(const float* __restrict__ in,
                 const float* __restrict__ W,
                 const float* __restrict__ bias,
                 float* __restrict__ out) {
    __shared__ float sIn[128 * PAD];    // node-major rows
    __shared__ float sWt[D * PADW];     // k-major: sWt[k*PADW + o]
    const int tid = threadIdx.x;
    const int nodeBase = blockIdx.x * 128;

    // Stage W transposed: read [o][k] float4, store 4 scalars to [k][o].
    for (int i = tid; i < D * 16; i += 256) {
        int o = i >> 4, kv = (i & 15) * 4;
        float4 wv = *(const float4*)&W[o * D + kv];
        sWt[(kv + 0) * PADW + o] = wv.x;
        sWt[(kv + 1) * PADW + o] = wv.y;
        sWt[(kv + 2) * PADW + o] = wv.z;
        sWt[(kv + 3) * PADW + o] = wv.w;
    }
    // Stage input tile (zero-fill past N_NODES).
    for (int i = tid; i < 128 * 16; i += 256) {
        int r = i >> 4, kv = (i & 15) * 4;
        int node = nodeBase + r;
        float4 v = make_float4(0.f, 0.f, 0.f, 0.f);
        if (node < N_NODES) v = *(const float4*)&in[node * D + kv];
        *(float4*)&sIn[r * PAD + kv] = v;
    }
    __syncthreads();

    const int tx = tid & 7;          // 8 tx -> dims {8tx .. 8tx+7}
    const int ty = tid >> 3;         // 32 ty -> nodes {4ty .. 4ty+3}
    const int c0 = tx * 8;
    const int r0 = ty * 4;

    u64t acc[4][4];                  // [node][dim-pair]
#pragma unroll
    for (int r = 0; r < 4; r++)
#pragma unroll
        for (int p = 0; p < 4; p++) acc[r][p] = pk2(0.f, 0.f);

#pragma unroll 4
    for (int k4 = 0; k4 < D; k4 += 4) {
        float4 a4[4];
#pragma unroll
        for (int r = 0; r < 4; r++) a4[r] = *(const float4*)&sIn[(r0 + r) * PAD + k4];
#pragma unroll
        for (int j = 0; j < 4; j++) {
            float4 w0 = *(const float4*)&sWt[(k4 + j) * PADW + c0];
            float4 w1 = *(const float4*)&sWt[(k4 + j) * PADW + c0 + 4];
            u64t wp0 = pk2(w0.x, w0.y), wp1 = pk2(w0.z, w0.w);
            u64t wp2 = pk2(w1.x, w1.y), wp3 = pk2(w1.z, w1.w);
#pragma unroll
            for (int r = 0; r < 4; r++) {
                float av = (j == 0) ? a4[r].x : (j == 1) ? a4[r].y : (j == 2) ? a4[r].z : a4[r].w;
                u64t ap = pk2(av, av);
                fma2(acc[r][0], ap, wp0);
                fma2(acc[r][1], ap, wp1);
                fma2(acc[r][2], ap, wp2);
                fma2(acc[r][3], ap, wp3);
            }
        }
    }

    float4 b0 = *(const float4*)&bias[c0];
    float4 b1 = *(const float4*)&bias[c0 + 4];

#pragma unroll
    for (int r = 0; r < 4; r++) {
        int node = nodeBase + r0 + r;
        if (node < N_NODES) {
            float v0, v1, v2, v3, v4, v5, v6, v7;
            upk2(v0, v1, acc[r][0]);
            upk2(v2, v3, acc[r][1]);
            upk2(v4, v5, acc[r][2]);
            upk2(v6, v7, acc[r][3]);
            float4 o0 = make_float4(fmaxf(v0 + b0.x, 0.f), fmaxf(v1 + b0.y, 0.f),
                                    fmaxf(v2 + b0.z, 0.f), fmaxf(v3 + b0.w, 0.f));
            float4 o1 = make_float4(fmaxf(v4 + b1.x, 0.f), fmaxf(v5 + b1.y, 0.f),
                                    fmaxf(v6 + b1.z, 0.f), fmaxf(v7 + b1.w, 0.f));
            *(float4*)&out[node * D + c0] = o0;
            *(float4*)&out[node * D + c0 + 4] = o1;
        }
    }
}

// ---------------------------------------------------------------------------
__global__ void zero_out_kernel(float* __restrict__ out, int n) {
    int i = blockIdx.x * blockDim.x + threadIdx.x;
    if (i < n) out[i] = 0.0f;
}

// batch is sorted: register accumulator, flush on graph-id change only.
__global__ void pool_kernel(const float* __restrict__ x,
                            const int* __restrict__ batch,
                            float* __restrict__ out, int chunk) {
    int d = threadIdx.x;
    int n0 = blockIdx.x * chunk;
    int n1 = n0 + chunk;
    if (n1 > N_NODES) n1 = N_NODES;
    if (n0 >= n1) return;
    float acc = 0.0f;
    int cur = batch[n0];
    for (int n = n0; n < n1; n++) {
        int g = batch[n];
        if (g != cur) {
            atomicAdd(&out[cur * D + d], acc);
            acc = 0.0f;
            cur = g;
        }
        acc += x[n * D + d];
    }
    atomicAdd(&out[cur * D + d], acc);
}

// ---------------------------------------------------------------------------
extern "C" void kernel_launch(void* const* d_in, const int* in_sizes, int n_in,
                              void* d_out, int out_size) {
    const float* x     = (const float*)d_in[0];
    const int*   ei    = (const int*)d_in[1];
    const int*   eei   = (const int*)d_in[2];
    const int*   batch = (const int*)d_in[3];
    const float* Ws    = (const float*)d_in[4];
    const float* bs    = (const float*)d_in[5];
    float*       out   = (float*)d_out;

    float4 *bufA, *bufB;
    int *counts, *bucket;
    cudaGetSymbolAddress((void**)&bufA, g_bufA);
    cudaGetSymbolAddress((void**)&bufB, g_bufB);
    cudaGetSymbolAddress((void**)&counts, g_counts);
    cudaGetSymbolAddress((void**)&bucket, g_bucket);
    int *c0 = counts, *c1 = counts + N_NODES;
    int *b0 = bucket, *b1 = bucket + N_NODES * CAP;

    const int* src1 = ei;   const int* dst1 = ei + N_EDGES;
    const int* src2 = eei;  const int* dst2 = eei + N_EDGES;

    // ---- Build bucket adjacency for both graphs (scan-free) ----
    const int nBlocks = (N_NODES + 255) / 256;
    const int eBlocks = (N_EDGES + 255) / 256;
    zero_counts_kernel<<<nBlocks, 256>>>(c0, c1);
    build_kernel<<<dim3(eBlocks, 2), 256>>>(src1, dst1, src2, dst2, c0, c1, b0, b1);

    // ---- 4 layers ----
    const int gatherBlocks = (N_NODES + 15) / 16;
    const int gemmBlocks = (N_NODES + 127) / 128;

    const float4* xcur = (const float4*)x;
    for (int i = 0; i < NLAYERS; i++) {
        gather_kernel<<<gatherBlocks, 256>>>(xcur, c0, b0, bufB);
        gemm_relu_kernel<<<gemmBlocks, 256>>>((const float*)bufB, Ws + i * D * D,
                                              bs + i * D, (float*)bufB);
        gather_kernel<<<gatherBlocks, 256>>>(bufB, c1, b1, bufA);
        xcur = bufA;
    }

    zero_out_kernel<<<(NGRAPHS * D + 255) / 256, 256>>>(out, NGRAPHS * D);
    pool_kernel<<<(N_NODES + 127) / 128, 64>>>((const float*)xcur, batch, out, 128);
}

// round 10
// speedup vs baseline: 1.0079x; 1.0079x over previous
#include <cuda_runtime.h>

#define N_NODES 50000
#define N_EDGES 800000
#define D 64
#define NLAYERS 4
#define NGRAPHS 128
#define PAD 68
#define CAP 64   // max in-degree slots; Poisson(16) -> P(deg>=64) ~ 1e-21

// Scratch (all __device__ globals per harness rules)
__device__ float4 g_bufA[N_NODES * (D / 4)];
__device__ float4 g_bufB[N_NODES * (D / 4)];
__device__ int g_counts[2][N_NODES];
__device__ int g_bucket[2][N_NODES * CAP];

// ---------------------------------------------------------------------------
// Scan-free adjacency build: fixed-capacity buckets, rebuilt every launch.
// ---------------------------------------------------------------------------
__global__ void zero_counts_kernel(int* c0, int* c1) {
    int i = blockIdx.x * blockDim.x + threadIdx.x;
    if (i < N_NODES) { c0[i] = 0; c1[i] = 0; }
}

__global__ void build_kernel(const int* __restrict__ src0, const int* __restrict__ dst0,
                             const int* __restrict__ src1, const int* __restrict__ dst1,
                             int* c0, int* c1, int* b0, int* b1) {
    int e = blockIdx.x * blockDim.x + threadIdx.x;
    if (e >= N_EDGES) return;
    if (blockIdx.y == 0) {
        int d = dst0[e];
        int slot = atomicAdd(&c0[d], 1);
        if (slot < CAP) b0[d * CAP + slot] = src0[e];
    } else {
        int d = dst1[e];
        int slot = atomicAdd(&c1[d], 1);
        if (slot < CAP) b1[d * CAP + slot] = src1[e];
    }
}

// ---------------------------------------------------------------------------
// GIN aggregate as pure gather: out[n] = x[n] + sum_{e: dst=n} x[src[e]]
// ---------------------------------------------------------------------------
__global__ void gather_kernel(const float4* __restrict__ x,
                              const int* __restrict__ cnt,
                              const int* __restrict__ bucket,
                              float4* __restrict__ out) {
    int lane = threadIdx.x & 15;
    int n = blockIdx.x * 16 + (threadIdx.x >> 4);
    if (n >= N_NODES) return;
    int deg = cnt[n];
    if (deg > CAP) deg = CAP;
    const int* __restrict__ lst = bucket + n * CAP;
    float4 acc = x[n * 16 + lane];
    int j = 0;
    for (; j + 4 <= deg; j += 4) {
        int s0 = lst[j];
        int s1 = lst[j + 1];
        int s2 = lst[j + 2];
        int s3 = lst[j + 3];
        float4 v0 = x[s0 * 16 + lane];
        float4 v1 = x[s1 * 16 + lane];
        float4 v2 = x[s2 * 16 + lane];
        float4 v3 = x[s3 * 16 + lane];
        acc.x += (v0.x + v1.x) + (v2.x + v3.x);
        acc.y += (v0.y + v1.y) + (v2.y + v3.y);
        acc.z += (v0.z + v1.z) + (v2.z + v3.z);
        acc.w += (v0.w + v1.w) + (v2.w + v3.w);
    }
    for (; j < deg; j++) {
        int s = lst[j];
        float4 v = x[s * 16 + lane];
        acc.x += v.x; acc.y += v.y; acc.z += v.z; acc.w += v.w;
    }
    out[n * 16 + lane] = acc;
}

// ---------------------------------------------------------------------------
// out = relu(in @ W^T + b). 128-node tile, 256 threads (8 warps).
// Warp layout: ty=tid&31 -> node lane, tx=tid>>5 -> dim group of 8.
// Each thread: 4 nodes {ty, ty+32, ty+64, ty+96} x 8 dims {8tx..8tx+7}.
// -> W loads are warp-uniform BROADCASTS (crossbar ~free); a loads are
//    conflict-free (stride PAD=68 => bank 4l mod 32 per 8-lane phase).
// In-place safe (tile staged via smem before any store by this block).
// ---------------------------------------------------------------------------
__global__ void __launch_bounds__(256, 2)
gemm_relu_kernel(const float* __restrict__ in,
                 const float* __restrict__ W,
                 const float* __restrict__ bias,
                 float* __restrict__ out) {
    __shared__ float sIn[128 * PAD];
    __shared__ float sW[D * PAD];
    const int tid = threadIdx.x;
    const int nodeBase = blockIdx.x * 128;

    // Stage W (o-major rows, padded): coalesced, conflict-free.
    for (int i = tid; i < D * 16; i += 256) {
        int o = i >> 4, kv = (i & 15) * 4;
        *(float4*)&sW[o * PAD + kv] = *(const float4*)&W[o * D + kv];
    }
    // Stage input tile (zero-fill past N_NODES).
    for (int i = tid; i < 128 * 16; i += 256) {
        int r = i >> 4, kv = (i & 15) * 4;
        int node = nodeBase + r;
        float4 v = make_float4(0.f, 0.f, 0.f, 0.f);
        if (node < N_NODES) v = *(const float4*)&in[node * D + kv];
        *(float4*)&sIn[r * PAD + kv] = v;
    }
    __syncthreads();

    const int ty = tid & 31;         // node lane
    const int tx = tid >> 5;         // dim group
    const int c0 = tx * 8;

    float acc[4][8];
#pragma unroll
    for (int r = 0; r < 4; r++)
#pragma unroll
        for (int c = 0; c < 8; c++) acc[r][c] = 0.f;

#pragma unroll 4
    for (int k4 = 0; k4 < D; k4 += 4) {
        float4 a[4];
#pragma unroll
        for (int r = 0; r < 4; r++)
            a[r] = *(const float4*)&sIn[(ty + 32 * r) * PAD + k4];
        float4 w[8];
#pragma unroll
        for (int c = 0; c < 8; c++)
            w[c] = *(const float4*)&sW[(c0 + c) * PAD + k4];   // warp-uniform broadcast
#pragma unroll
        for (int r = 0; r < 4; r++)
#pragma unroll
            for (int c = 0; c < 8; c++) {
                acc[r][c] = fmaf(a[r].x, w[c].x, acc[r][c]);
                acc[r][c] = fmaf(a[r].y, w[c].y, acc[r][c]);
                acc[r][c] = fmaf(a[r].z, w[c].z, acc[r][c]);
                acc[r][c] = fmaf(a[r].w, w[c].w, acc[r][c]);
            }
    }

    float bv[8];
#pragma unroll
    for (int c = 0; c < 8; c++) bv[c] = bias[c0 + c];

#pragma unroll
    for (int r = 0; r < 4; r++) {
        int node = nodeBase + ty + 32 * r;
        if (node < N_NODES) {
            float4 o0 = make_float4(fmaxf(acc[r][0] + bv[0], 0.f),
                                    fmaxf(acc[r][1] + bv[1], 0.f),
                                    fmaxf(acc[r][2] + bv[2], 0.f),
                                    fmaxf(acc[r][3] + bv[3], 0.f));
            float4 o1 = make_float4(fmaxf(acc[r][4] + bv[4], 0.f),
                                    fmaxf(acc[r][5] + bv[5], 0.f),
                                    fmaxf(acc[r][6] + bv[6], 0.f),
                                    fmaxf(acc[r][7] + bv[7], 0.f));
            *(float4*)&out[node * D + c0] = o0;
            *(float4*)&out[node * D + c0 + 4] = o1;
        }
    }
}

// ---------------------------------------------------------------------------
__global__ void zero_out_kernel(float* __restrict__ out, int n) {
    int i = blockIdx.x * blockDim.x + threadIdx.x;
    if (i < n) out[i] = 0.0f;
}

// batch is sorted: register accumulator, flush on graph-id change only.
__global__ void pool_kernel(const float* __restrict__ x,
                            const int* __restrict__ batch,
                            float* __restrict__ out, int chunk) {
    int d = threadIdx.x;
    int n0 = blockIdx.x * chunk;
    int n1 = n0 + chunk;
    if (n1 > N_NODES) n1 = N_NODES;
    if (n0 >= n1) return;
    float acc = 0.0f;
    int cur = batch[n0];
    for (int n = n0; n < n1; n++) {
        int g = batch[n];
        if (g != cur) {
            atomicAdd(&out[cur * D + d], acc);
            acc = 0.0f;
            cur = g;
        }
        acc += x[n * D + d];
    }
    atomicAdd(&out[cur * D + d], acc);
}

// ---------------------------------------------------------------------------
extern "C" void kernel_launch(void* const* d_in, const int* in_sizes, int n_in,
                              void* d_out, int out_size) {
    const float* x     = (const float*)d_in[0];
    const int*   ei    = (const int*)d_in[1];
    const int*   eei   = (const int*)d_in[2];
    const int*   batch = (const int*)d_in[3];
    const float* Ws    = (const float*)d_in[4];
    const float* bs    = (const float*)d_in[5];
    float*       out   = (float*)d_out;

    float4 *bufA, *bufB;
    int *counts, *bucket;
    cudaGetSymbolAddress((void**)&bufA, g_bufA);
    cudaGetSymbolAddress((void**)&bufB, g_bufB);
    cudaGetSymbolAddress((void**)&counts, g_counts);
    cudaGetSymbolAddress((void**)&bucket, g_bucket);
    int *c0 = counts, *c1 = counts + N_NODES;
    int *b0 = bucket, *b1 = bucket + N_NODES * CAP;

    const int* src1 = ei;   const int* dst1 = ei + N_EDGES;
    const int* src2 = eei;  const int* dst2 = eei + N_EDGES;

    // ---- Build bucket adjacency for both graphs (scan-free) ----
    const int nBlocks = (N_NODES + 255) / 256;
    const int eBlocks = (N_EDGES + 255) / 256;
    zero_counts_kernel<<<nBlocks, 256>>>(c0, c1);
    build_kernel<<<dim3(eBlocks, 2), 256>>>(src1, dst1, src2, dst2, c0, c1, b0, b1);

    // ---- 4 layers ----
    const int gatherBlocks = (N_NODES + 15) / 16;
    const int gemmBlocks = (N_NODES + 127) / 128;

    const float4* xcur = (const float4*)x;
    for (int i = 0; i < NLAYERS; i++) {
        gather_kernel<<<gatherBlocks, 256>>>(xcur, c0, b0, bufB);
        gemm_relu_kernel<<<gemmBlocks, 256>>>((const float*)bufB, Ws + i * D * D,
                                              bs + i * D, (float*)bufB);
        gather_kernel<<<gatherBlocks, 256>>>(bufB, c1, b1, bufA);
        xcur = bufA;
    }

    zero_out_kernel<<<(NGRAPHS * D + 255) / 256, 256>>>(out, NGRAPHS * D);
    pool_kernel<<<(N_NODES + 127) / 128, 64>>>((const float*)xcur, batch, out, 128);
}

// round 11
// speedup vs baseline: 1.0855x; 1.0770x over previous
#include <cuda_runtime.h>

#define N_NODES 50000
#define N_EDGES 800000
#define D 64
#define NLAYERS 4
#define NGRAPHS 128
#define CAP 64   // max in-degree slots; Poisson(16) -> P(deg>=64) ~ 1e-21

// GEMM smem: input tile 128x68 fp32 + W 64x136 (hi,lo interleaved tf32)
#define GEMM_SMEM_BYTES (128 * 68 * 4 + 64 * 136 * 4)   // 69632

// Scratch (all __device__ globals per harness rules)
__device__ float4 g_bufA[N_NODES * (D / 4)];
__device__ float4 g_bufB[N_NODES * (D / 4)];
__device__ int g_counts[2][N_NODES];
__device__ int g_bucket[2][N_NODES * CAP];

// ---------------------------------------------------------------------------
// Scan-free adjacency build: fixed-capacity buckets, rebuilt every launch.
// ---------------------------------------------------------------------------
__global__ void zero_counts_kernel(int* c0, int* c1) {
    int i = blockIdx.x * blockDim.x + threadIdx.x;
    if (i < N_NODES) { c0[i] = 0; c1[i] = 0; }
}

__global__ void build_kernel(const int* __restrict__ src0, const int* __restrict__ dst0,
                             const int* __restrict__ src1, const int* __restrict__ dst1,
                             int* c0, int* c1, int* b0, int* b1) {
    int e = blockIdx.x * blockDim.x + threadIdx.x;
    if (e >= N_EDGES) return;
    if (blockIdx.y == 0) {
        int d = dst0[e];
        int slot = atomicAdd(&c0[d], 1);
        if (slot < CAP) b0[d * CAP + slot] = src0[e];
    } else {
        int d = dst1[e];
        int slot = atomicAdd(&c1[d], 1);
        if (slot < CAP) b1[d * CAP + slot] = src1[e];
    }
}

// ---------------------------------------------------------------------------
// GIN aggregate as pure gather: out[n] = x[n] + sum_{e: dst=n} x[src[e]]
// ---------------------------------------------------------------------------
__global__ void gather_kernel(const float4* __restrict__ x,
                              const int* __restrict__ cnt,
                              const int* __restrict__ bucket,
                              float4* __restrict__ out) {
    int lane = threadIdx.x & 15;
    int n = blockIdx.x * 16 + (threadIdx.x >> 4);
    if (n >= N_NODES) return;
    int deg = cnt[n];
    if (deg > CAP) deg = CAP;
    const int* __restrict__ lst = bucket + n * CAP;
    float4 acc = x[n * 16 + lane];
    int j = 0;
    for (; j + 4 <= deg; j += 4) {
        int s0 = lst[j];
        int s1 = lst[j + 1];
        int s2 = lst[j + 2];
        int s3 = lst[j + 3];
        float4 v0 = x[s0 * 16 + lane];
        float4 v1 = x[s1 * 16 + lane];
        float4 v2 = x[s2 * 16 + lane];
        float4 v3 = x[s3 * 16 + lane];
        acc.x += (v0.x + v1.x) + (v2.x + v3.x);
        acc.y += (v0.y + v1.y) + (v2.y + v3.y);
        acc.z += (v0.z + v1.z) + (v2.z + v3.z);
        acc.w += (v0.w + v1.w) + (v2.w + v3.w);
    }
    for (; j < deg; j++) {
        int s = lst[j];
        float4 v = x[s * 16 + lane];
        acc.x += v.x; acc.y += v.y; acc.z += v.z; acc.w += v.w;
    }
    out[n * 16 + lane] = acc;
}

// ---------------------------------------------------------------------------
// tf32 helpers
// ---------------------------------------------------------------------------
__device__ __forceinline__ unsigned f2tf32(float x) {
    unsigned r;
    asm("cvt.rna.tf32.f32 %0, %1;" : "=r"(r) : "f"(x));
    return r;
}

__device__ __forceinline__ void mma_tf32(float c[4],
                                         unsigned a0, unsigned a1, unsigned a2, unsigned a3,
                                         unsigned b0, unsigned b1) {
    asm volatile(
        "mma.sync.aligned.m16n8k8.row.col.f32.tf32.tf32.f32 "
        "{%0,%1,%2,%3}, {%4,%5,%6,%7}, {%8,%9}, {%0,%1,%2,%3};"
        : "+f"(c[0]), "+f"(c[1]), "+f"(c[2]), "+f"(c[3])
        : "r"(a0), "r"(a1), "r"(a2), "r"(a3), "r"(b0), "r"(b1));
}

// ---------------------------------------------------------------------------
// out = relu(in @ W^T + b) via 3xTF32 tensor-core MMA (fp32-grade precision).
// 128-node tile, 256 threads (8 warps, 16 nodes/warp).
// W staged as interleaved (hi,lo) tf32 pairs; A split hi/lo on the fly.
// In-place safe (tile staged via smem before any store by this block).
// ---------------------------------------------------------------------------
__global__ void __launch_bounds__(256, 3)
gemm_relu_kernel(const float* __restrict__ in,
                 const float* __restrict__ W,
                 const float* __restrict__ bias,
                 float* __restrict__ out) {
    extern __shared__ float sm[];
    float* sIn = sm;                                  // [128][68] fp32
    unsigned* sW = (unsigned*)(sm + 128 * 68);        // [64][136]: [o][2k]=hi, [o][2k+1]=lo
    const int tid = threadIdx.x;
    const int nodeBase = blockIdx.x * 128;

    // Stage W -> (hi, lo) tf32 pairs.
    for (int i = tid; i < D * D; i += 256) {
        int o = i >> 6, k = i & 63;
        float x = W[i];
        unsigned hi = f2tf32(x);
        unsigned lo = f2tf32(x - __uint_as_float(hi));
        sW[o * 136 + 2 * k]     = hi;
        sW[o * 136 + 2 * k + 1] = lo;
    }
    // Stage input tile (zero-fill past N_NODES).
    for (int i = tid; i < 128 * 16; i += 256) {
        int r = i >> 4, kv = (i & 15) * 4;
        int node = nodeBase + r;
        float4 v = make_float4(0.f, 0.f, 0.f, 0.f);
        if (node < N_NODES) v = *(const float4*)&in[node * D + kv];
        *(float4*)&sIn[r * 68 + kv] = v;
    }
    __syncthreads();

    const int warp = tid >> 5;
    const int lane = tid & 31;
    const int grp  = lane >> 2;     // 0..7  (node row within 16 / n within 8)
    const int tig  = lane & 3;      // 0..3  (k within 4 / col pair)
    const int rowBase = warp * 16;  // warp's nodes within the 128-tile

    float c[8][4];                  // [n-tile][c0..c3]
#pragma unroll
    for (int nt = 0; nt < 8; nt++)
#pragma unroll
        for (int q = 0; q < 4; q++) c[nt][q] = 0.f;

#pragma unroll
    for (int kc = 0; kc < 8; kc++) {
        const int k0 = kc * 8;
        // A fragment (m16k8, row-major): rows grp/grp+8, cols tig/tig+4
        float a0f = sIn[(rowBase + grp    ) * 68 + k0 + tig];
        float a1f = sIn[(rowBase + grp + 8) * 68 + k0 + tig];
        float a2f = sIn[(rowBase + grp    ) * 68 + k0 + tig + 4];
        float a3f = sIn[(rowBase + grp + 8) * 68 + k0 + tig + 4];
        unsigned aH0 = f2tf32(a0f), aH1 = f2tf32(a1f), aH2 = f2tf32(a2f), aH3 = f2tf32(a3f);
        unsigned aL0 = f2tf32(a0f - __uint_as_float(aH0));
        unsigned aL1 = f2tf32(a1f - __uint_as_float(aH1));
        unsigned aL2 = f2tf32(a2f - __uint_as_float(aH2));
        unsigned aL3 = f2tf32(a3f - __uint_as_float(aH3));
#pragma unroll
        for (int nt = 0; nt < 8; nt++) {
            // B fragment (k8n8, col-major): b0 k=tig, b1 k=tig+4, n=grp
            uint2 bp0 = *(const uint2*)&sW[(nt * 8 + grp) * 136 + 2 * (k0 + tig)];
            uint2 bp1 = *(const uint2*)&sW[(nt * 8 + grp) * 136 + 2 * (k0 + tig + 4)];
            mma_tf32(c[nt], aH0, aH1, aH2, aH3, bp0.x, bp1.x);   // hi*hi
            mma_tf32(c[nt], aL0, aL1, aL2, aL3, bp0.x, bp1.x);   // lo*hi
            mma_tf32(c[nt], aH0, aH1, aH2, aH3, bp0.y, bp1.y);   // hi*lo
        }
    }

    // Epilogue: bias + relu + store (c0,c1 -> row grp; c2,c3 -> row grp+8)
    const int n0 = nodeBase + rowBase + grp;
    const int n1 = n0 + 8;
#pragma unroll
    for (int nt = 0; nt < 8; nt++) {
        int o = nt * 8 + 2 * tig;
        float2 bv = *(const float2*)&bias[o];
        if (n0 < N_NODES) {
            float2 v = make_float2(fmaxf(c[nt][0] + bv.x, 0.f),
                                   fmaxf(c[nt][1] + bv.y, 0.f));
            *(float2*)&out[n0 * D + o] = v;
        }
        if (n1 < N_NODES) {
            float2 v = make_float2(fmaxf(c[nt][2] + bv.x, 0.f),
                                   fmaxf(c[nt][3] + bv.y, 0.f));
            *(float2*)&out[n1 * D + o] = v;
        }
    }
}

// ---------------------------------------------------------------------------
__global__ void zero_out_kernel(float* __restrict__ out, int n) {
    int i = blockIdx.x * blockDim.x + threadIdx.x;
    if (i < n) out[i] = 0.0f;
}

// batch is sorted: register accumulator, flush on graph-id change only.
__global__ void pool_kernel(const float* __restrict__ x,
                            const int* __restrict__ batch,
                            float* __restrict__ out, int chunk) {
    int d = threadIdx.x;
    int n0 = blockIdx.x * chunk;
    int n1 = n0 + chunk;
    if (n1 > N_NODES) n1 = N_NODES;
    if (n0 >= n1) return;
    float acc = 0.0f;
    int cur = batch[n0];
    for (int n = n0; n < n1; n++) {
        int g = batch[n];
        if (g != cur) {
            atomicAdd(&out[cur * D + d], acc);
            acc = 0.0f;
            cur = g;
        }
        acc += x[n * D + d];
    }
    atomicAdd(&out[cur * D + d], acc);
}

// ---------------------------------------------------------------------------
extern "C" void kernel_launch(void* const* d_in, const int* in_sizes, int n_in,
                              void* d_out, int out_size) {
    const float* x     = (const float*)d_in[0];
    const int*   ei    = (const int*)d_in[1];
    const int*   eei   = (const int*)d_in[2];
    const int*   batch = (const int*)d_in[3];
    const float* Ws    = (const float*)d_in[4];
    const float* bs    = (const float*)d_in[5];
    float*       out   = (float*)d_out;

    // Raise dynamic-smem limit for the MMA GEMM (idempotent; not an allocation).
    cudaFuncSetAttribute(gemm_relu_kernel,
                         cudaFuncAttributeMaxDynamicSharedMemorySize, GEMM_SMEM_BYTES);

    float4 *bufA, *bufB;
    int *counts, *bucket;
    cudaGetSymbolAddress((void**)&bufA, g_bufA);
    cudaGetSymbolAddress((void**)&bufB, g_bufB);
    cudaGetSymbolAddress((void**)&counts, g_counts);
    cudaGetSymbolAddress((void**)&bucket, g_bucket);
    int *c0 = counts, *c1 = counts + N_NODES;
    int *b0 = bucket, *b1 = bucket + N_NODES * CAP;

    const int* src1 = ei;   const int* dst1 = ei + N_EDGES;
    const int* src2 = eei;  const int* dst2 = eei + N_EDGES;

    // ---- Build bucket adjacency for both graphs (scan-free) ----
    const int nBlocks = (N_NODES + 255) / 256;
    const int eBlocks = (N_EDGES + 255) / 256;
    zero_counts_kernel<<<nBlocks, 256>>>(c0, c1);
    build_kernel<<<dim3(eBlocks, 2), 256>>>(src1, dst1, src2, dst2, c0, c1, b0, b1);

    // ---- 4 layers ----
    const int gatherBlocks = (N_NODES + 15) / 16;
    const int gemmBlocks = (N_NODES + 127) / 128;

    const float4* xcur = (const float4*)x;
    for (int i = 0; i < NLAYERS; i++) {
        gather_kernel<<<gatherBlocks, 256>>>(xcur, c0, b0, bufB);
        gemm_relu_kernel<<<gemmBlocks, 256, GEMM_SMEM_BYTES>>>((const float*)bufB,
                                                               Ws + i * D * D,
                                                               bs + i * D, (float*)bufB);
        gather_kernel<<<gatherBlocks, 256>>>(bufB, c1, b1, bufA);
        xcur = bufA;
    }

    zero_out_kernel<<<(NGRAPHS * D + 255) / 256, 256>>>(out, NGRAPHS * D);
    pool_kernel<<<(N_NODES + 127) / 128, 64>>>((const float*)xcur, batch, out, 128);
}

// round 12
// speedup vs baseline: 1.0949x; 1.0087x over previous
#include <cuda_runtime.h>

#define N_NODES 50000
#define N_EDGES 800000
#define D 64
#define NLAYERS 4
#define NGRAPHS 128
#define CAP 64   // max in-degree slots; Poisson(16) -> P(deg>=64) ~ 1e-21

// GEMM smem: A 128x(64 hi,lo pairs) + W 64x(64 hi,lo pairs), row stride 136 u32
#define GEMM_SMEM_BYTES ((128 * 136 + 64 * 136) * 4)   // 104448

// Scratch (all __device__ globals per harness rules)
__device__ float4 g_bufA[N_NODES * (D / 4)];
__device__ float4 g_bufB[N_NODES * (D / 4)];
__device__ int g_counts[2][N_NODES];
__device__ int g_bucket[2][N_NODES * CAP];

// ---------------------------------------------------------------------------
// Scan-free adjacency build: fixed-capacity buckets, rebuilt every launch.
// ---------------------------------------------------------------------------
__global__ void zero_counts_kernel(int* c0, int* c1) {
    int i = blockIdx.x * blockDim.x + threadIdx.x;
    if (i < N_NODES) { c0[i] = 0; c1[i] = 0; }
}

__global__ void build_kernel(const int* __restrict__ src0, const int* __restrict__ dst0,
                             const int* __restrict__ src1, const int* __restrict__ dst1,
                             int* c0, int* c1, int* b0, int* b1) {
    int e = blockIdx.x * blockDim.x + threadIdx.x;
    if (e >= N_EDGES) return;
    if (blockIdx.y == 0) {
        int d = dst0[e];
        int slot = atomicAdd(&c0[d], 1);
        if (slot < CAP) b0[d * CAP + slot] = src0[e];
    } else {
        int d = dst1[e];
        int slot = atomicAdd(&c1[d], 1);
        if (slot < CAP) b1[d * CAP + slot] = src1[e];
    }
}

// ---------------------------------------------------------------------------
// GIN aggregate as pure gather: out[n] = x[n] + sum_{e: dst=n} x[src[e]]
// ---------------------------------------------------------------------------
__global__ void gather_kernel(const float4* __restrict__ x,
                              const int* __restrict__ cnt,
                              const int* __restrict__ bucket,
                              float4* __restrict__ out) {
    int lane = threadIdx.x & 15;
    int n = blockIdx.x * 16 + (threadIdx.x >> 4);
    if (n >= N_NODES) return;
    int deg = cnt[n];
    if (deg > CAP) deg = CAP;
    const int* __restrict__ lst = bucket + n * CAP;
    float4 acc = x[n * 16 + lane];
    int j = 0;
    for (; j + 4 <= deg; j += 4) {
        int s0 = lst[j];
        int s1 = lst[j + 1];
        int s2 = lst[j + 2];
        int s3 = lst[j + 3];
        float4 v0 = x[s0 * 16 + lane];
        float4 v1 = x[s1 * 16 + lane];
        float4 v2 = x[s2 * 16 + lane];
        float4 v3 = x[s3 * 16 + lane];
        acc.x += (v0.x + v1.x) + (v2.x + v3.x);
        acc.y += (v0.y + v1.y) + (v2.y + v3.y);
        acc.z += (v0.z + v1.z) + (v2.z + v3.z);
        acc.w += (v0.w + v1.w) + (v2.w + v3.w);
    }
    for (; j < deg; j++) {
        int s = lst[j];
        float4 v = x[s * 16 + lane];
        acc.x += v.x; acc.y += v.y; acc.z += v.z; acc.w += v.w;
    }
    out[n * 16 + lane] = acc;
}

// ---------------------------------------------------------------------------
// tf32 helpers
// ---------------------------------------------------------------------------
__device__ __forceinline__ unsigned f2tf32(float x) {
    unsigned r;
    asm("cvt.rna.tf32.f32 %0, %1;" : "=r"(r) : "f"(x));
    return r;
}

__device__ __forceinline__ void mma_tf32(float c[4],
                                         unsigned a0, unsigned a1, unsigned a2, unsigned a3,
                                         unsigned b0, unsigned b1) {
    asm volatile(
        "mma.sync.aligned.m16n8k8.row.col.f32.tf32.tf32.f32 "
        "{%0,%1,%2,%3}, {%4,%5,%6,%7}, {%8,%9}, {%0,%1,%2,%3};"
        : "+f"(c[0]), "+f"(c[1]), "+f"(c[2]), "+f"(c[3])
        : "r"(a0), "r"(a1), "r"(a2), "r"(a3), "r"(b0), "r"(b1));
}

// ---------------------------------------------------------------------------
// out = relu(in @ W^T + b) via 3xTF32 MMA with PRE-SPLIT (hi,lo) operands.
// 128-node tile, 512 threads (16 warps = 8 m-tiles x 2 n-halves).
// Inner loop is pure LDS.64 + HMMA — all cvt done in staging.
// In-place safe (tile staged via smem before any store by this block).
// ---------------------------------------------------------------------------
__global__ void __launch_bounds__(512, 2)
gemm_relu_kernel(const float* __restrict__ in,
                 const float* __restrict__ W,
                 const float* __restrict__ bias,
                 float* __restrict__ out) {
    extern __shared__ unsigned sm[];
    unsigned* sA = sm;                       // [128][136]: [r][2k]=hi, [2k+1]=lo
    unsigned* sW = sm + 128 * 136;           // [64][136]:  [o][2k]=hi, [2k+1]=lo
    const int tid = threadIdx.x;
    const int nodeBase = blockIdx.x * 128;

    // Stage W -> (hi,lo) pairs. 4096 elems / 512 threads = 8 each.
    for (int i = tid; i < D * D; i += 512) {
        int o = i >> 6, k = i & 63;
        float x = W[i];
        unsigned hi = f2tf32(x);
        unsigned lo = f2tf32(x - __uint_as_float(hi));
        *(uint2*)&sW[o * 136 + 2 * k] = make_uint2(hi, lo);
    }
    // Stage A -> (hi,lo) pairs (zero-fill past N_NODES).
    for (int i = tid; i < 128 * 16; i += 512) {
        int r = i >> 4, kv = (i & 15) * 4;
        int node = nodeBase + r;
        float4 v = make_float4(0.f, 0.f, 0.f, 0.f);
        if (node < N_NODES) v = *(const float4*)&in[node * D + kv];
        unsigned h0 = f2tf32(v.x), h1 = f2tf32(v.y), h2 = f2tf32(v.z), h3 = f2tf32(v.w);
        unsigned l0 = f2tf32(v.x - __uint_as_float(h0));
        unsigned l1 = f2tf32(v.y - __uint_as_float(h1));
        unsigned l2 = f2tf32(v.z - __uint_as_float(h2));
        unsigned l3 = f2tf32(v.w - __uint_as_float(h3));
        uint4* p = (uint4*)&sA[r * 136 + 2 * kv];
        p[0] = make_uint4(h0, l0, h1, l1);
        p[1] = make_uint4(h2, l2, h3, l3);
    }
    __syncthreads();

    const int warp = tid >> 5;
    const int lane = tid & 31;
    const int grp  = lane >> 2;      // 0..7
    const int tig  = lane & 3;       // 0..3
    const int m    = warp & 7;       // m-tile: rows m*16 .. m*16+15
    const int h    = warp >> 3;      // n-half: dims h*32 .. h*32+31
    const int row0 = m * 16 + grp;
    const int row1 = row0 + 8;

    float c[4][4];
#pragma unroll
    for (int nt = 0; nt < 4; nt++)
#pragma unroll
        for (int q = 0; q < 4; q++) c[nt][q] = 0.f;

#pragma unroll
    for (int kc = 0; kc < 8; kc++) {
        const int k0 = kc * 8;
        uint2 a0 = *(const uint2*)&sA[row0 * 136 + 2 * (k0 + tig)];      // (hi,lo)
        uint2 a1 = *(const uint2*)&sA[row1 * 136 + 2 * (k0 + tig)];
        uint2 a2 = *(const uint2*)&sA[row0 * 136 + 2 * (k0 + tig + 4)];
        uint2 a3 = *(const uint2*)&sA[row1 * 136 + 2 * (k0 + tig + 4)];
#pragma unroll
        for (int nt = 0; nt < 4; nt++) {
            const int o = h * 32 + nt * 8 + grp;
            uint2 b0 = *(const uint2*)&sW[o * 136 + 2 * (k0 + tig)];
            uint2 b1 = *(const uint2*)&sW[o * 136 + 2 * (k0 + tig + 4)];
            mma_tf32(c[nt], a0.x, a1.x, a2.x, a3.x, b0.x, b1.x);   // hi*hi
            mma_tf32(c[nt], a0.y, a1.y, a2.y, a3.y, b0.x, b1.x);   // lo*hi
            mma_tf32(c[nt], a0.x, a1.x, a2.x, a3.x, b0.y, b1.y);   // hi*lo
        }
    }

    // Epilogue: bias + relu + store (c0,c1 -> row0; c2,c3 -> row1)
    const int n0 = nodeBase + row0;
    const int n1 = nodeBase + row1;
#pragma unroll
    for (int nt = 0; nt < 4; nt++) {
        int o = h * 32 + nt * 8 + 2 * tig;
        float2 bv = *(const float2*)&bias[o];
        if (n0 < N_NODES) {
            float2 v = make_float2(fmaxf(c[nt][0] + bv.x, 0.f),
                                   fmaxf(c[nt][1] + bv.y, 0.f));
            *(float2*)&out[n0 * D + o] = v;
        }
        if (n1 < N_NODES) {
            float2 v = make_float2(fmaxf(c[nt][2] + bv.x, 0.f),
                                   fmaxf(c[nt][3] + bv.y, 0.f));
            *(float2*)&out[n1 * D + o] = v;
        }
    }
}

// ---------------------------------------------------------------------------
__global__ void zero_out_kernel(float* __restrict__ out, int n) {
    int i = blockIdx.x * blockDim.x + threadIdx.x;
    if (i < n) out[i] = 0.0f;
}

// batch is sorted: register accumulator, flush on graph-id change only.
__global__ void pool_kernel(const float* __restrict__ x,
                            const int* __restrict__ batch,
                            float* __restrict__ out, int chunk) {
    int d = threadIdx.x;
    int n0 = blockIdx.x * chunk;
    int n1 = n0 + chunk;
    if (n1 > N_NODES) n1 = N_NODES;
    if (n0 >= n1) return;
    float acc = 0.0f;
    int cur = batch[n0];
    for (int n = n0; n < n1; n++) {
        int g = batch[n];
        if (g != cur) {
            atomicAdd(&out[cur * D + d], acc);
            acc = 0.0f;
            cur = g;
        }
        acc += x[n * D + d];
    }
    atomicAdd(&out[cur * D + d], acc);
}

// ---------------------------------------------------------------------------
extern "C" void kernel_launch(void* const* d_in, const int* in_sizes, int n_in,
                              void* d_out, int out_size) {
    const float* x     = (const float*)d_in[0];
    const int*   ei    = (const int*)d_in[1];
    const int*   eei   = (const int*)d_in[2];
    const int*   batch = (const int*)d_in[3];
    const float* Ws    = (const float*)d_in[4];
    const float* bs    = (const float*)d_in[5];
    float*       out   = (float*)d_out;

    // Raise dynamic-smem limit for the MMA GEMM (idempotent; not an allocation).
    cudaFuncSetAttribute(gemm_relu_kernel,
                         cudaFuncAttributeMaxDynamicSharedMemorySize, GEMM_SMEM_BYTES);

    float4 *bufA, *bufB;
    int *counts, *bucket;
    cudaGetSymbolAddress((void**)&bufA, g_bufA);
    cudaGetSymbolAddress((void**)&bufB, g_bufB);
    cudaGetSymbolAddress((void**)&counts, g_counts);
    cudaGetSymbolAddress((void**)&bucket, g_bucket);
    int *c0 = counts, *c1 = counts + N_NODES;
    int *b0 = bucket, *b1 = bucket + N_NODES * CAP;

    const int* src1 = ei;   const int* dst1 = ei + N_EDGES;
    const int* src2 = eei;  const int* dst2 = eei + N_EDGES;

    // ---- Build bucket adjacency for both graphs (scan-free) ----
    const int nBlocks = (N_NODES + 255) / 256;
    const int eBlocks = (N_EDGES + 255) / 256;
    zero_counts_kernel<<<nBlocks, 256>>>(c0, c1);
    build_kernel<<<dim3(eBlocks, 2), 256>>>(src1, dst1, src2, dst2, c0, c1, b0, b1);

    // ---- 4 layers ----
    const int gatherBlocks = (N_NODES + 15) / 16;
    const int gemmBlocks = (N_NODES + 127) / 128;

    const float4* xcur = (const float4*)x;
    for (int i = 0; i < NLAYERS; i++) {
        gather_kernel<<<gatherBlocks, 256>>>(xcur, c0, b0, bufB);
        gemm_relu_kernel<<<gemmBlocks, 512, GEMM_SMEM_BYTES>>>((const float*)bufB,
                                                               Ws + i * D * D,
                                                               bs + i * D, (float*)bufB);
        gather_kernel<<<gatherBlocks, 256>>>(bufB, c1, b1, bufA);
        xcur = bufA;
    }

    zero_out_kernel<<<(NGRAPHS * D + 255) / 256, 256>>>(out, NGRAPHS * D);
    pool_kernel<<<(N_NODES + 127) / 128, 64>>>((const float*)xcur, batch, out, 128);
}